// round 2
// baseline (speedup 1.0000x reference)
#include <cuda_runtime.h>
#include <cuda_bf16.h>

// SSIM loss, fused: 5 box filters via separable rolling sums + SSIM + mean.
// Inputs: x, y each (32,1,1024,1024) fp32. Output: 1 float = 1 - mean(ssim_map).

#define W 1024
#define H 1024
#define NIMG 32
#define COLS_PER_BLOCK 256
#define ROWS_PER_STRIP 64
#define GRID_X (W / COLS_PER_BLOCK)          // 4
#define GRID_Y (H / ROWS_PER_STRIP)          // 16
#define NBLOCKS (GRID_X * GRID_Y * NIMG)     // 2048

__device__ float g_partials[NBLOCKS];

__device__ __forceinline__ void load_hrow(const float* __restrict__ xp,
                                          const float* __restrict__ yp,
                                          int r, int c,
                                          float& hx, float& hy,
                                          float& hxx, float& hyy, float& hxy) {
    if ((unsigned)r < (unsigned)H) {
        int base = r * W + c;
        float xc = xp[base];
        float yc = yp[base];
        float xl = (c > 0)     ? xp[base - 1] : 0.0f;
        float yl = (c > 0)     ? yp[base - 1] : 0.0f;
        float xr = (c < W - 1) ? xp[base + 1] : 0.0f;
        float yr = (c < W - 1) ? yp[base + 1] : 0.0f;
        hx  = xl + xc + xr;
        hy  = yl + yc + yr;
        hxx = xl * xl + xc * xc + xr * xr;
        hyy = yl * yl + yc * yc + yr * yr;
        hxy = xl * yl + xc * yc + xr * yr;
    } else {
        hx = 0.0f; hy = 0.0f; hxx = 0.0f; hyy = 0.0f; hxy = 0.0f;
    }
}

__global__ __launch_bounds__(COLS_PER_BLOCK)
void ssim_partial_kernel(const float* __restrict__ x,
                         const float* __restrict__ y) {
    const int c   = blockIdx.x * COLS_PER_BLOCK + threadIdx.x;
    const int img = blockIdx.z;
    const int r0  = blockIdx.y * ROWS_PER_STRIP;

    const float* xp = x + (size_t)img * W * H;
    const float* yp = y + (size_t)img * W * H;

    const float inv9 = 1.0f / 9.0f;
    const float C1v = 0.01f * 0.01f;
    const float C2v = 0.03f * 0.03f;
    const float EPSv = 1e-8f;

    // ring: prev (r-1), curr (r), next (r+1)
    float phx, phy, phxx, phyy, phxy;
    float qhx, qhy, qhxx, qhyy, qhxy;
    float nhx, nhy, nhxx, nhyy, nhxy;

    load_hrow(xp, yp, r0 - 1, c, phx, phy, phxx, phyy, phxy);
    load_hrow(xp, yp, r0,     c, qhx, qhy, qhxx, qhyy, qhxy);

    float acc = 0.0f;

#pragma unroll 4
    for (int r = r0; r < r0 + ROWS_PER_STRIP; ++r) {
        load_hrow(xp, yp, r + 1, c, nhx, nhy, nhxx, nhyy, nhxy);

        float Sx  = phx  + qhx  + nhx;
        float Sy  = phy  + qhy  + nhy;
        float Sxx = phxx + qhxx + nhxx;
        float Syy = phyy + qhyy + nhyy;
        float Sxy = phxy + qhxy + nhxy;

        float mux  = Sx * inv9;
        float muy  = Sy * inv9;
        float muxy = mux * muy;
        float mux2 = mux * mux;
        float muy2 = muy * muy;

        float sxy = Sxy * inv9 - muxy;          // sigma_xy
        float sx  = Sxx * inv9 - mux2;          // sigma_x
        float sy  = Syy * inv9 - muy2;          // sigma_y

        float A = 2.0f * muxy + C1v;
        float B = 2.0f * sxy  + C2v;
        float Cc = mux2 + muy2 + C1v;
        float D  = sx + sy + C2v;

        acc += __fdividef(A * B, Cc * D + EPSv);

        // rotate ring
        phx = qhx;  phy = qhy;  phxx = qhxx;  phyy = qhyy;  phxy = qhxy;
        qhx = nhx;  qhy = nhy;  qhxx = nhxx;  qhyy = nhyy;  qhxy = nhxy;
    }

    // warp reduce
    for (int off = 16; off > 0; off >>= 1)
        acc += __shfl_down_sync(0xFFFFFFFFu, acc, off);

    __shared__ float warp_sums[COLS_PER_BLOCK / 32];
    int lane = threadIdx.x & 31;
    int wid  = threadIdx.x >> 5;
    if (lane == 0) warp_sums[wid] = acc;
    __syncthreads();

    if (wid == 0) {
        float v = (lane < COLS_PER_BLOCK / 32) ? warp_sums[lane] : 0.0f;
        for (int off = 4; off > 0; off >>= 1)
            v += __shfl_down_sync(0xFFFFFFFFu, v, off);
        if (lane == 0) {
            int blin = (blockIdx.z * gridDim.y + blockIdx.y) * gridDim.x + blockIdx.x;
            g_partials[blin] = v;
        }
    }
}

__global__ __launch_bounds__(256)
void ssim_finalize_kernel(float* __restrict__ out) {
    int tid = threadIdx.x;
    double s = 0.0;
    for (int i = tid; i < NBLOCKS; i += 256)
        s += (double)g_partials[i];

    // warp reduce (double)
    for (int off = 16; off > 0; off >>= 1)
        s += __shfl_down_sync(0xFFFFFFFFu, s, off);

    __shared__ double warp_sums[8];
    int lane = tid & 31;
    int wid  = tid >> 5;
    if (lane == 0) warp_sums[wid] = s;
    __syncthreads();

    if (wid == 0) {
        double v = (lane < 8) ? warp_sums[lane] : 0.0;
        for (int off = 4; off > 0; off >>= 1)
            v += __shfl_down_sync(0xFFFFFFFFu, v, off);
        if (lane == 0) {
            double mean = v / (double)((size_t)NIMG * W * H);
            out[0] = (float)(1.0 - mean);
        }
    }
}

extern "C" void kernel_launch(void* const* d_in, const int* in_sizes, int n_in,
                              void* d_out, int out_size) {
    const float* x = (const float*)d_in[0];
    const float* y = (const float*)d_in[1];
    float* out = (float*)d_out;

    dim3 grid(GRID_X, GRID_Y, NIMG);
    dim3 block(COLS_PER_BLOCK);
    ssim_partial_kernel<<<grid, block>>>(x, y);
    ssim_finalize_kernel<<<1, 256>>>(out);
}

// round 5
// speedup vs baseline: 1.2129x; 1.2129x over previous
#include <cuda_runtime.h>
#include <cstdint>

// SSIM loss fused single-pass: packed f32x2 math, 4 cols/thread, scaled-by-81
// SSIM identity, last-block finalize. x,y: (32,1,1024,1024) fp32 -> 1 float.

#define W 1024
#define H 1024
#define NIMG 32
#define TPB 128
#define CPT 4
#define COLS_PER_BLOCK (TPB * CPT)          // 512
#define GRID_X (W / COLS_PER_BLOCK)         // 2
#define ROWS_PER_STRIP 32
#define GRID_Y (H / ROWS_PER_STRIP)         // 32
#define NBLOCKS (GRID_X * GRID_Y * NIMG)    // 2048
#define NPIX ((double)NIMG * W * H)

__device__ float g_partials[NBLOCKS];
__device__ unsigned int g_count = 0;

// ---- packed f32x2 helpers (sm_103a) ----
__device__ __forceinline__ uint64_t pk(float lo, float hi) {
    uint64_t r;
    asm("mov.b64 %0, {%1, %2};" : "=l"(r) : "f"(lo), "f"(hi));
    return r;
}
__device__ __forceinline__ void upk(uint64_t v, float& lo, float& hi) {
    asm("mov.b64 {%0, %1}, %2;" : "=f"(lo), "=f"(hi) : "l"(v));
}
__device__ __forceinline__ uint64_t f2add(uint64_t a, uint64_t b) {
    uint64_t r;
    asm("add.rn.f32x2 %0, %1, %2;" : "=l"(r) : "l"(a), "l"(b));
    return r;
}
__device__ __forceinline__ uint64_t f2mul(uint64_t a, uint64_t b) {
    uint64_t r;
    asm("mul.rn.f32x2 %0, %1, %2;" : "=l"(r) : "l"(a), "l"(b));
    return r;
}
__device__ __forceinline__ uint64_t f2fma(uint64_t a, uint64_t b, uint64_t c) {
    uint64_t r;
    asm("fma.rn.f32x2 %0, %1, %2, %3;" : "=l"(r) : "l"(a), "l"(b), "l"(c));
    return r;
}

// Compute one horizontal-filtered row for this thread's 4 columns, packed as
// column-pairs: h[0,1]=hx(lo,hi) h[2,3]=hy h[4,5]=h(x^2+y^2) h[6,7]=h(xy).
__device__ __forceinline__ void hrow(const float* __restrict__ xp,
                                     const float* __restrict__ yp,
                                     int r, int c0, uint64_t h[8]) {
    if ((unsigned)r >= (unsigned)H) {
#pragma unroll
        for (int i = 0; i < 8; ++i) h[i] = 0;
        return;
    }
    const int base = r * W + c0;
    const float4 vx = *reinterpret_cast<const float4*>(xp + base);
    const float4 vy = *reinterpret_cast<const float4*>(yp + base);
    const float xl = (c0 > 0)       ? xp[base - 1] : 0.0f;
    const float xr = (c0 + 4 < W)   ? xp[base + 4] : 0.0f;
    const float yl = (c0 > 0)       ? yp[base - 1] : 0.0f;
    const float yr = (c0 + 4 < W)   ? yp[base + 4] : 0.0f;

    // 6-element sequences a=[xl,vx...,xr], b=[yl,vy...,yr] as 5 shifted pairs.
    uint64_t PA0 = pk(xl, vx.x),   MA0 = pk(vx.x, vx.y);
    uint64_t PA1 = pk(vx.y, vx.z), MA1 = pk(vx.z, vx.w);
    uint64_t PA2 = pk(vx.w, xr);
    uint64_t PB0 = pk(yl, vy.x),   MB0 = pk(vy.x, vy.y);
    uint64_t PB1 = pk(vy.y, vy.z), MB1 = pk(vy.z, vy.w);
    uint64_t PB2 = pk(vy.w, yr);

    // ss = x^2 + y^2 ; pp = x*y (elementwise, so shifted pairs come free)
    uint64_t S0 = f2fma(PA0, PA0, f2mul(PB0, PB0));
    uint64_t S1 = f2fma(PA1, PA1, f2mul(PB1, PB1));
    uint64_t S2 = f2fma(PA2, PA2, f2mul(PB2, PB2));
    uint64_t SM0 = f2fma(MA0, MA0, f2mul(MB0, MB0));
    uint64_t SM1 = f2fma(MA1, MA1, f2mul(MB1, MB1));
    uint64_t Q0 = f2mul(PA0, PB0);
    uint64_t Q1 = f2mul(PA1, PB1);
    uint64_t Q2 = f2mul(PA2, PB2);
    uint64_t QM0 = f2mul(MA0, MB0);
    uint64_t QM1 = f2mul(MA1, MB1);

    // 3-tap horizontal: pair(lo) = P0+M0+P1, pair(hi) = P1+M1+P2
    h[0] = f2add(f2add(PA0, MA0), PA1);
    h[1] = f2add(f2add(PA1, MA1), PA2);
    h[2] = f2add(f2add(PB0, MB0), PB1);
    h[3] = f2add(f2add(PB1, MB1), PB2);
    h[4] = f2add(f2add(S0, SM0), S1);
    h[5] = f2add(f2add(S1, SM1), S2);
    h[6] = f2add(f2add(Q0, QM0), Q1);
    h[7] = f2add(f2add(Q1, QM1), Q2);
}

__global__ __launch_bounds__(TPB)
void ssim_fused_kernel(const float* __restrict__ x,
                       const float* __restrict__ y,
                       float* __restrict__ out) {
    const int tid = threadIdx.x;
    const int c0  = (blockIdx.x * TPB + tid) * CPT;
    const int img = blockIdx.z;
    const int r0  = blockIdx.y * ROWS_PER_STRIP;

    const float* xp = x + (size_t)img * W * H;
    const float* yp = y + (size_t)img * W * H;

    // Scaled constants: ssim = A*B / (C*D + 6561*eps), all sums unnormalized.
    const uint64_t C1S  = pk(81.0f * 1e-4f, 81.0f * 1e-4f);       // 81*C1
    const uint64_t C2S  = pk(81.0f * 9e-4f, 81.0f * 9e-4f);       // 81*C2
    const uint64_t EPSS = pk(6.561e-5f, 6.561e-5f);               // 6561*eps
    const uint64_t TWO  = pk(2.0f, 2.0f);
    const uint64_t NTWO = pk(-2.0f, -2.0f);
    const uint64_t NONE = pk(-1.0f, -1.0f);
    const uint64_t NINE = pk(9.0f, 9.0f);
    const uint64_t EI8T = pk(18.0f, 18.0f);

    uint64_t p[8], q[8], n[8];
    hrow(xp, yp, r0 - 1, c0, p);
    hrow(xp, yp, r0,     c0, q);

    float acc = 0.0f;

#pragma unroll 2
    for (int r = r0; r < r0 + ROWS_PER_STRIP; ++r) {
        hrow(xp, yp, r + 1, c0, n);

        uint64_t Sx0  = f2add(f2add(p[0], q[0]), n[0]);
        uint64_t Sx1  = f2add(f2add(p[1], q[1]), n[1]);
        uint64_t Sy0  = f2add(f2add(p[2], q[2]), n[2]);
        uint64_t Sy1  = f2add(f2add(p[3], q[3]), n[3]);
        uint64_t Sss0 = f2add(f2add(p[4], q[4]), n[4]);
        uint64_t Sss1 = f2add(f2add(p[5], q[5]), n[5]);
        uint64_t Sxy0 = f2add(f2add(p[6], q[6]), n[6]);
        uint64_t Sxy1 = f2add(f2add(p[7], q[7]), n[7]);

#pragma unroll
        for (int half = 0; half < 2; ++half) {
            uint64_t sx  = half ? Sx1  : Sx0;
            uint64_t sy  = half ? Sy1  : Sy0;
            uint64_t sss = half ? Sss1 : Sss0;
            uint64_t sxy = half ? Sxy1 : Sxy0;

            uint64_t ab  = f2mul(sx, sy);
            uint64_t t2  = f2fma(sx, sx, f2mul(sy, sy));
            uint64_t A   = f2fma(ab, TWO, C1S);            // 2ab + 81C1
            uint64_t Bp  = f2fma(ab, NTWO, C2S);
            uint64_t B   = f2fma(sxy, EI8T, Bp);           // 18Sxy - 2ab + 81C2
            uint64_t Cq  = f2add(t2, C1S);                 // sx^2+sy^2 + 81C1
            uint64_t Dp  = f2fma(t2, NONE, C2S);
            uint64_t D   = f2fma(sss, NINE, Dp);           // 9Sss - t2 + 81C2
            uint64_t num = f2mul(A, B);
            uint64_t den = f2fma(Cq, D, EPSS);

            float n0, n1, d0, d1;
            upk(num, n0, n1);
            upk(den, d0, d1);
            acc += __fdividef(n0, d0);
            acc += __fdividef(n1, d1);
        }

#pragma unroll
        for (int i = 0; i < 8; ++i) { p[i] = q[i]; q[i] = n[i]; }
    }

    // block reduction (float)
    for (int off = 16; off > 0; off >>= 1)
        acc += __shfl_down_sync(0xFFFFFFFFu, acc, off);

    __shared__ float warp_sums[TPB / 32];
    const int lane = tid & 31;
    const int wid  = tid >> 5;
    if (lane == 0) warp_sums[wid] = acc;
    __syncthreads();

    __shared__ bool is_last;
    if (tid == 0) {
        float v = warp_sums[0] + warp_sums[1] + warp_sums[2] + warp_sums[3];
        const int blin = (blockIdx.z * gridDim.y + blockIdx.y) * gridDim.x + blockIdx.x;
        g_partials[blin] = v;
        __threadfence();
        unsigned int prev = atomicAdd(&g_count, 1u);
        is_last = (prev == NBLOCKS - 1);
        if (is_last) g_count = 0;   // reset for next graph replay
    }
    __syncthreads();

    if (is_last) {
        __threadfence();
        double s = 0.0;
        for (int i = tid; i < NBLOCKS; i += TPB)
            s += (double)g_partials[i];

        for (int off = 16; off > 0; off >>= 1)
            s += __shfl_down_sync(0xFFFFFFFFu, s, off);

        __shared__ double dsum[TPB / 32];
        if (lane == 0) dsum[wid] = s;
        __syncthreads();
        if (tid == 0) {
            double v = dsum[0] + dsum[1] + dsum[2] + dsum[3];
            out[0] = (float)(1.0 - v / NPIX);
        }
    }
}

extern "C" void kernel_launch(void* const* d_in, const int* in_sizes, int n_in,
                              void* d_out, int out_size) {
    const float* x = (const float*)d_in[0];
    const float* y = (const float*)d_in[1];
    float* out = (float*)d_out;

    dim3 grid(GRID_X, GRID_Y, NIMG);
    ssim_fused_kernel<<<grid, TPB>>>(x, y, out);
}

// round 6
// speedup vs baseline: 1.2633x; 1.0415x over previous
#include <cuda_runtime.h>
#include <cstdint>

// SSIM loss fused single-pass: packed f32x2 math, 4 cols/thread, scaled-by-81
// identity, two-buffer vertical ring (period-2 -> zero rotation MOVs),
// combined divides, last-block finalize. x,y: (32,1,1024,1024) fp32 -> 1 float.

#define W 1024
#define H 1024
#define NIMG 32
#define TPB 128
#define CPT 4
#define COLS_PER_BLOCK (TPB * CPT)          // 512
#define GRID_X (W / COLS_PER_BLOCK)         // 2
#define ROWS_PER_STRIP 32
#define GRID_Y (H / ROWS_PER_STRIP)         // 32
#define NBLOCKS (GRID_X * GRID_Y * NIMG)    // 2048
#define NPIX ((double)NIMG * W * H)

__device__ float g_partials[NBLOCKS];
__device__ unsigned int g_count = 0;

// ---- packed f32x2 helpers (sm_103a) ----
__device__ __forceinline__ uint64_t pk(float lo, float hi) {
    uint64_t r;
    asm("mov.b64 %0, {%1, %2};" : "=l"(r) : "f"(lo), "f"(hi));
    return r;
}
__device__ __forceinline__ void upk(uint64_t v, float& lo, float& hi) {
    asm("mov.b64 {%0, %1}, %2;" : "=f"(lo), "=f"(hi) : "l"(v));
}
__device__ __forceinline__ uint64_t f2add(uint64_t a, uint64_t b) {
    uint64_t r;
    asm("add.rn.f32x2 %0, %1, %2;" : "=l"(r) : "l"(a), "l"(b));
    return r;
}
__device__ __forceinline__ uint64_t f2mul(uint64_t a, uint64_t b) {
    uint64_t r;
    asm("mul.rn.f32x2 %0, %1, %2;" : "=l"(r) : "l"(a), "l"(b));
    return r;
}
__device__ __forceinline__ uint64_t f2fma(uint64_t a, uint64_t b, uint64_t c) {
    uint64_t r;
    asm("fma.rn.f32x2 %0, %1, %2, %3;" : "=l"(r) : "l"(a), "l"(b), "l"(c));
    return r;
}

struct HRow { uint64_t v[8]; };  // [0,1]=hx [2,3]=hy [4,5]=h(x^2+y^2) [6,7]=h(xy)

// One horizontal-filtered row for 4 columns, packed as column-pairs.
__device__ __forceinline__ void hrow(const float* __restrict__ xp,
                                     const float* __restrict__ yp,
                                     int r, int c0, HRow& h) {
    if ((unsigned)r >= (unsigned)H) {
#pragma unroll
        for (int i = 0; i < 8; ++i) h.v[i] = 0;
        return;
    }
    const int base = r * W + c0;
    const float4 vx = *reinterpret_cast<const float4*>(xp + base);
    const float4 vy = *reinterpret_cast<const float4*>(yp + base);
    const float xl = (c0 > 0)     ? xp[base - 1] : 0.0f;
    const float xr = (c0 + 4 < W) ? xp[base + 4] : 0.0f;
    const float yl = (c0 > 0)     ? yp[base - 1] : 0.0f;
    const float yr = (c0 + 4 < W) ? yp[base + 4] : 0.0f;

    uint64_t PA0 = pk(xl, vx.x),   MA0 = pk(vx.x, vx.y);
    uint64_t PA1 = pk(vx.y, vx.z), MA1 = pk(vx.z, vx.w);
    uint64_t PA2 = pk(vx.w, xr);
    uint64_t PB0 = pk(yl, vy.x),   MB0 = pk(vy.x, vy.y);
    uint64_t PB1 = pk(vy.y, vy.z), MB1 = pk(vy.z, vy.w);
    uint64_t PB2 = pk(vy.w, yr);

    uint64_t S0  = f2fma(PA0, PA0, f2mul(PB0, PB0));
    uint64_t S1  = f2fma(PA1, PA1, f2mul(PB1, PB1));
    uint64_t S2  = f2fma(PA2, PA2, f2mul(PB2, PB2));
    uint64_t SM0 = f2fma(MA0, MA0, f2mul(MB0, MB0));
    uint64_t SM1 = f2fma(MA1, MA1, f2mul(MB1, MB1));
    uint64_t Q0  = f2mul(PA0, PB0);
    uint64_t Q1  = f2mul(PA1, PB1);
    uint64_t Q2  = f2mul(PA2, PB2);
    uint64_t QM0 = f2mul(MA0, MB0);
    uint64_t QM1 = f2mul(MA1, MB1);

    h.v[0] = f2add(f2add(PA0, MA0), PA1);
    h.v[1] = f2add(f2add(PA1, MA1), PA2);
    h.v[2] = f2add(f2add(PB0, MB0), PB1);
    h.v[3] = f2add(f2add(PB1, MB1), PB2);
    h.v[4] = f2add(f2add(S0, SM0), S1);
    h.v[5] = f2add(f2add(S1, SM1), S2);
    h.v[6] = f2add(f2add(Q0, QM0), Q1);
    h.v[7] = f2add(f2add(Q1, QM1), Q2);
}

// One output row: S = A + N; SSIM from S; then Aout = B + N, Bout = N.
__device__ __forceinline__ void row_step(const float* __restrict__ xp,
                                         const float* __restrict__ yp,
                                         int r, int c0,
                                         const HRow& A, const HRow& B,
                                         HRow& Aout, HRow& Bout,
                                         float& acc) {
    const uint64_t C1S  = pk(81.0f * 1e-4f, 81.0f * 1e-4f);
    const uint64_t C2S  = pk(81.0f * 9e-4f, 81.0f * 9e-4f);
    const uint64_t EPSS = pk(6.561e-5f, 6.561e-5f);
    const uint64_t TWO  = pk(2.0f, 2.0f);
    const uint64_t NTWO = pk(-2.0f, -2.0f);
    const uint64_t NONE = pk(-1.0f, -1.0f);
    const uint64_t NINE = pk(9.0f, 9.0f);
    const uint64_t EI8T = pk(18.0f, 18.0f);

    HRow N;
    hrow(xp, yp, r + 1, c0, N);

    uint64_t S[8];
#pragma unroll
    for (int i = 0; i < 8; ++i) S[i] = f2add(A.v[i], N.v[i]);

#pragma unroll
    for (int half = 0; half < 2; ++half) {
        uint64_t sx  = S[half];
        uint64_t sy  = S[2 + half];
        uint64_t sss = S[4 + half];
        uint64_t sxy = S[6 + half];

        uint64_t ab  = f2mul(sx, sy);
        uint64_t t2  = f2fma(sx, sx, f2mul(sy, sy));
        uint64_t Aq  = f2fma(ab, TWO, C1S);            // 2ab + 81C1
        uint64_t Bq  = f2fma(sxy, EI8T, f2fma(ab, NTWO, C2S));
        uint64_t Cq  = f2add(t2, C1S);
        uint64_t Dq  = f2fma(sss, NINE, f2fma(t2, NONE, C2S));
        uint64_t num = f2mul(Aq, Bq);
        uint64_t den = f2fma(Cq, Dq, EPSS);

        float n0, n1, d0, d1;
        upk(num, n0, n1);
        upk(den, d0, d1);
        // n0/d0 + n1/d1 with a single approx divide
        acc += __fdividef(fmaf(n0, d1, n1 * d0), d0 * d1);
    }

#pragma unroll
    for (int i = 0; i < 8; ++i) Aout.v[i] = f2add(B.v[i], N.v[i]);
    Bout = N;
}

__global__ __launch_bounds__(TPB)
void ssim_fused_kernel(const float* __restrict__ x,
                       const float* __restrict__ y,
                       float* __restrict__ out) {
    const int tid = threadIdx.x;
    const int c0  = (blockIdx.x * TPB + tid) * CPT;
    const int img = blockIdx.z;
    const int r0  = blockIdx.y * ROWS_PER_STRIP;

    const float* xp = x + (size_t)img * W * H;
    const float* yp = y + (size_t)img * W * H;

    // Prologue: A = h(r0-1) + h(r0), B = h(r0)
    HRow A0, B0;
    {
        HRow pm1;
        hrow(xp, yp, r0 - 1, c0, pm1);
        hrow(xp, yp, r0,     c0, B0);
#pragma unroll
        for (int i = 0; i < 8; ++i) A0.v[i] = f2add(pm1.v[i], B0.v[i]);
    }

    float acc = 0.0f;

#pragma unroll 1
    for (int rr = 0; rr < ROWS_PER_STRIP; rr += 2) {
        HRow A1, B1;
        row_step(xp, yp, r0 + rr,     c0, A0, B0, A1, B1, acc);
        row_step(xp, yp, r0 + rr + 1, c0, A1, B1, A0, B0, acc);
    }

    // block reduction (float)
    for (int off = 16; off > 0; off >>= 1)
        acc += __shfl_down_sync(0xFFFFFFFFu, acc, off);

    __shared__ float warp_sums[TPB / 32];
    const int lane = tid & 31;
    const int wid  = tid >> 5;
    if (lane == 0) warp_sums[wid] = acc;
    __syncthreads();

    __shared__ bool is_last;
    if (tid == 0) {
        float v = warp_sums[0] + warp_sums[1] + warp_sums[2] + warp_sums[3];
        const int blin = (blockIdx.z * gridDim.y + blockIdx.y) * gridDim.x + blockIdx.x;
        g_partials[blin] = v;
        __threadfence();
        unsigned int prev = atomicAdd(&g_count, 1u);
        is_last = (prev == NBLOCKS - 1);
        if (is_last) g_count = 0;   // reset for next graph replay
    }
    __syncthreads();

    if (is_last) {
        __threadfence();
        double s = 0.0;
        for (int i = tid; i < NBLOCKS; i += TPB)
            s += (double)g_partials[i];

        for (int off = 16; off > 0; off >>= 1)
            s += __shfl_down_sync(0xFFFFFFFFu, s, off);

        __shared__ double dsum[TPB / 32];
        if (lane == 0) dsum[wid] = s;
        __syncthreads();
        if (tid == 0) {
            double v = dsum[0] + dsum[1] + dsum[2] + dsum[3];
            out[0] = (float)(1.0 - v / NPIX);
        }
    }
}

extern "C" void kernel_launch(void* const* d_in, const int* in_sizes, int n_in,
                              void* d_out, int out_size) {
    const float* x = (const float*)d_in[0];
    const float* y = (const float*)d_in[1];
    float* out = (float*)d_out;

    dim3 grid(GRID_X, GRID_Y, NIMG);
    ssim_fused_kernel<<<grid, TPB>>>(x, y, out);
}